// round 8
// baseline (speedup 1.0000x reference)
#include <cuda_runtime.h>
#include <cuda_fp16.h>
#include <mma.h>
#include <cstdint>

using namespace nvcuda;

// ============================ problem constants ============================
static constexpr int E_TOTAL = 500000;
static constexpr int MEM_D   = 100;
static constexpr int EDGE_D  = 172;
static constexpr int HID     = 128;
static constexpr int IN_D    = 472;   // 100 + 100 + 100 + 172
static constexpr int K_PAD   = 480;   // padded K (zeros beyond 472), 5 chunks of 96
static constexpr int KCHUNK  = 96;
static constexpr int NCHUNK  = K_PAD / KCHUNK;   // 5
static constexpr int TILE_M  = 128;   // edges per CTA
static constexpr int NTHREADS = 256;  // 8 warps, warp w owns rows [16w, 16w+16)
static constexpr int NUM_TILES = (E_TOTAL + TILE_M - 1) / TILE_M;  // 3907

// smem strides (halves), both multiples of 8 for 16B-aligned WMMA rows
static constexpr int A_LD = 104;      // KCHUNK 96 + 8 pad
static constexpr int B_LD = 136;      // HID 128 + 8 pad

// ============================ smem layout (bytes) ============================
static constexpr int SO_SRC = 0;                   // int[128]
static constexpr int SO_DST = SO_SRC + 512;        // int[128]
static constexpr int SO_DT  = SO_DST + 512;        // float[128]
static constexpr int SO_EOF = SO_DT  + 512;        // int[128]
static constexpr int SO_MSK = SO_EOF + 512;        // float[128]
static constexpr int SO_B1  = SO_MSK + 512;        // float[128]
static constexpr int SO_W2  = SO_B1  + 512;        // float[128]
static constexpr int SO_A   = SO_W2  + 512;        // 3584: A tile, 128 x A_LD halves
static constexpr int A_BYTES = TILE_M * A_LD * 2;  // 26624
static constexpr int SO_B   = SO_A + A_BYTES;      // B tile, 96 x B_LD halves
static constexpr int B_BYTES = KCHUNK * B_LD * 2;  // 26112
static constexpr int SMEM_DYN = SO_B + B_BYTES;    // 56320 B

// fp16 w1, row-major [K_PAD x HID], zero-padded rows 472..479.
__device__ __half g_w1_f16[K_PAD * HID];

// Accurate cos for |x| up to ~1e4: Cody-Waite 2-step reduction + MUFU cos.
__device__ __forceinline__ float fast_cos(float x) {
    float k = rintf(x * 0.15915494309189535f);   // x / 2pi
    float y = fmaf(-k, 6.28125f, x);             // 6.28125 exact in 9 bits
    y = fmaf(-k, 1.9353072e-3f, y);              // 2pi = 6.28125 + 1.9353072e-3
    return __cosf(y);
}

// ============================ prologue: w1 -> fp16 ============================
__global__ void prep_w1_kernel(const float* __restrict__ w1) {
    int idx = blockIdx.x * blockDim.x + threadIdx.x;   // 0 .. 480*128-1
    int k = idx / HID;
    float v = (k < IN_D) ? w1[idx] : 0.0f;   // idx == k*HID + h for k < IN_D
    g_w1_f16[idx] = __float2half(v);
}

// ============================ main kernel ============================
__global__ void __launch_bounds__(NTHREADS)
tgn_growth_kernel(const int* __restrict__ src, const int* __restrict__ dst,
                  const float* __restrict__ t, const float* __restrict__ edge_attr,
                  const float* __restrict__ memory, const float* __restrict__ last_update,
                  const float* __restrict__ time_w, const float* __restrict__ time_b,
                  const float* __restrict__ b1, const float* __restrict__ w2,
                  const float* __restrict__ b2, float* __restrict__ out) {
    extern __shared__ __align__(16) char smem[];
    const int tid = threadIdx.x;
    const int wid = tid >> 5;
    const int lid = tid & 31;

    int*    sSrc = (int*)(smem + SO_SRC);
    int*    sDst = (int*)(smem + SO_DST);
    float*  sDt  = (float*)(smem + SO_DT);
    int*    sEof = (int*)(smem + SO_EOF);
    float*  sMsk = (float*)(smem + SO_MSK);
    float*  sB1  = (float*)(smem + SO_B1);
    float*  sW2  = (float*)(smem + SO_W2);
    __half* sA   = (__half*)(smem + SO_A);
    __half* sB   = (__half*)(smem + SO_B);

    // ---- per-tile scalar staging ----
    const int tile0 = blockIdx.x * TILE_M;
    if (tid < TILE_M) {
        int e = tile0 + tid;
        bool v = (e < E_TOTAL);
        int ec = v ? e : 0;
        int s = src[ec];
        sSrc[tid] = s * MEM_D;
        sDst[tid] = dst[ec] * MEM_D;
        sDt[tid]  = t[ec] - last_update[s];
        sEof[tid] = ec * EDGE_D;
        sMsk[tid] = v ? 1.0f : 0.0f;
        sB1[tid]  = b1[tid];
        sW2[tid]  = w2[tid];
    }
    __syncthreads();

    // ---- accumulators: warp wid owns rows [wid*16, wid*16+16), cols 0..127 ----
    wmma::fragment<wmma::accumulator, 16, 16, 16, float> acc[8];
    #pragma unroll
    for (int nt = 0; nt < 8; ++nt) wmma::fill_fragment(acc[nt], 0.0f);

    // ---- K-chunk loop ----
    for (int c = 0; c < NCHUNK; ++c) {
        const int kb = c * KCHUNK;

        // Stage A: gather/convert X chunk [128 rows x 96 halves] (pairs, coalesced).
        #pragma unroll 4
        for (int i = tid; i < TILE_M * (KCHUNK / 2); i += NTHREADS) {
            const int r  = i / (KCHUNK / 2);
            const int jp = i - r * (KCHUNK / 2);
            const int k0 = kb + (jp << 1);
            float x0 = 0.0f, x1 = 0.0f;
            if (k0 < MEM_D) {                       // src memory (region widths even: no straddle)
                float2 v2 = *reinterpret_cast<const float2*>(memory + sSrc[r] + k0);
                x0 = v2.x; x1 = v2.y;
            } else if (k0 < 2 * MEM_D) {            // dst memory
                float2 v2 = *reinterpret_cast<const float2*>(memory + sDst[r] + (k0 - MEM_D));
                x0 = v2.x; x1 = v2.y;
            } else if (k0 < 300) {                  // time encoding
                const int j = k0 - 200;
                float2 tw = *reinterpret_cast<const float2*>(time_w + j);
                float2 tb = *reinterpret_cast<const float2*>(time_b + j);
                float dtv = sDt[r];
                x0 = fast_cos(fmaf(dtv, tw.x, tb.x));
                x1 = fast_cos(fmaf(dtv, tw.y, tb.y));
            } else if (k0 < IN_D) {                 // edge attributes
                float2 v2 = *reinterpret_cast<const float2*>(edge_attr + sEof[r] + (k0 - 300));
                x0 = v2.x; x1 = v2.y;
            }                                       // else: K padding -> 0
            const float m = sMsk[r];
            __half2 h2 = __floats2half2_rn(x0 * m, x1 * m);
            *reinterpret_cast<__half2*>(sA + r * A_LD + (jp << 1)) = h2;
        }

        // Stage B: fp16 w1 chunk [96 rows x 128 halves] via uint4 (coalesced).
        #pragma unroll
        for (int i = tid; i < KCHUNK * 16; i += NTHREADS) {   // 16 uint4 per row
            const int row = i >> 4;
            const int q   = i & 15;
            uint4 v = *reinterpret_cast<const uint4*>(g_w1_f16 + (kb + row) * HID + q * 8);
            *reinterpret_cast<uint4*>(sB + row * B_LD + q * 8) = v;
        }
        __syncthreads();

        // WMMA: 6 k-steps x 8 n-tiles per warp.
        const __half* aBase = sA + (wid * 16) * A_LD;
        #pragma unroll
        for (int ks = 0; ks < KCHUNK / 16; ++ks) {
            wmma::fragment<wmma::matrix_a, 16, 16, 16, __half, wmma::row_major> af;
            wmma::load_matrix_sync(af, aBase + ks * 16, A_LD);
            #pragma unroll
            for (int nt = 0; nt < 8; ++nt) {
                wmma::fragment<wmma::matrix_b, 16, 16, 16, __half, wmma::row_major> bf;
                wmma::load_matrix_sync(bf, sB + (ks * 16) * B_LD + nt * 16, B_LD);
                wmma::mma_sync(acc[nt], af, bf, acc[nt]);
            }
        }
        __syncthreads();   // protect smem before next chunk's staging overwrites
    }

    // ---- epilogue: bias + ReLU + dot(w2) + b2, fused per warp ----
    // Scratch: each warp reuses its OWN 16 rows of the A region (warp-private).
    float* scratch = (float*)(sA + (wid * 16) * A_LD);   // needs 16*16*4 = 1KB < 3328B
    const float bias2 = b2[0];
    const int rrow = lid >> 1;            // 0..15
    const int cb   = (lid & 1) * 8;       // 0 or 8
    float partial = 0.0f;
    #pragma unroll
    for (int nt = 0; nt < 8; ++nt) {
        __syncwarp();
        wmma::store_matrix_sync(scratch, acc[nt], 16, wmma::mem_row_major);
        __syncwarp();
        #pragma unroll
        for (int j = 0; j < 8; ++j) {
            const int h = nt * 16 + cb + j;
            float v = scratch[rrow * 16 + cb + j] + sB1[h];
            v = fmaxf(v, 0.0f);
            partial = fmaf(v, sW2[h], partial);
        }
    }
    partial += __shfl_xor_sync(0xFFFFFFFFu, partial, 1);
    if ((lid & 1) == 0) {
        const int e = tile0 + wid * 16 + rrow;
        if (e < E_TOTAL) out[e] = partial + bias2;
    }
}

// ============================ launch ============================
extern "C" void kernel_launch(void* const* d_in, const int* in_sizes, int n_in,
                              void* d_out, int out_size) {
    (void)in_sizes; (void)n_in; (void)out_size;
    const int*   src         = (const int*)d_in[0];
    const int*   dst         = (const int*)d_in[1];
    const float* t           = (const float*)d_in[2];
    const float* edge_attr   = (const float*)d_in[3];
    const float* memory      = (const float*)d_in[4];
    const float* last_update = (const float*)d_in[5];
    const float* time_w      = (const float*)d_in[6];
    const float* time_b      = (const float*)d_in[7];
    const float* w1          = (const float*)d_in[8];
    const float* b1          = (const float*)d_in[9];
    const float* w2          = (const float*)d_in[10];
    const float* b2          = (const float*)d_in[11];
    float* out = (float*)d_out;

    prep_w1_kernel<<<(K_PAD * HID + 255) / 256, 256>>>(w1);

    cudaFuncSetAttribute(tgn_growth_kernel,
                         cudaFuncAttributeMaxDynamicSharedMemorySize, SMEM_DYN);
    tgn_growth_kernel<<<NUM_TILES, NTHREADS, SMEM_DYN>>>(
        src, dst, t, edge_attr, memory, last_update, time_w, time_b, b1, w2, b2, out);
}

// round 9
// speedup vs baseline: 1.6071x; 1.6071x over previous
#include <cuda_runtime.h>
#include <cuda_fp16.h>
#include <mma.h>
#include <cstdint>

using namespace nvcuda;

// ============================ problem constants ============================
static constexpr int E_TOTAL = 500000;
static constexpr int MEM_D   = 100;
static constexpr int EDGE_D  = 172;
static constexpr int HID     = 128;
static constexpr int IN_D    = 472;   // 100 + 100 + 100 + 172
static constexpr int K_PAD   = 480;   // padded K (zeros beyond 472)
static constexpr int KCHUNK  = 32;
static constexpr int NCHUNK  = K_PAD / KCHUNK;   // 15
static constexpr int TILE_M  = 128;   // edges per CTA
static constexpr int NTHREADS = 256;  // 8 warps: 4 m-groups x 2 n-groups
static constexpr int NUM_TILES = (E_TOTAL + TILE_M - 1) / TILE_M;  // 3907

// smem strides (halves): rows 16B-aligned
static constexpr int A_LD = 40;       // 32 + 8 pad  (80B rows, /16 ok)
static constexpr int B_LD = 136;      // 128 + 8 pad (272B rows)

// ============================ smem layout (bytes) ============================
static constexpr int SO_SRC  = 0;                    // int[128]
static constexpr int SO_DST  = SO_SRC  + 512;
static constexpr int SO_DT   = SO_DST  + 512;        // float[128]
static constexpr int SO_EOF  = SO_DT   + 512;
static constexpr int SO_MSK  = SO_EOF  + 512;
static constexpr int SO_B1   = SO_MSK  + 512;        // float[128]
static constexpr int SO_W2   = SO_B1   + 512;        // float[128]
static constexpr int SO_PART = SO_W2   + 512;        // float[256] partial sums
static constexpr int SO_BUF  = SO_PART + 1024;       // 4608
static constexpr int A_BYTES = TILE_M * A_LD * 2;    // 10240
static constexpr int B_BYTES = KCHUNK * B_LD * 2;    // 8704
static constexpr int SO_A0 = SO_BUF;
static constexpr int SO_A1 = SO_A0 + A_BYTES;
static constexpr int SO_B0 = SO_A1 + A_BYTES;
static constexpr int SO_B1b = SO_B0 + B_BYTES;
static constexpr int SMEM_DYN = SO_B1b + B_BYTES;    // 42496 B -> 2 CTAs/SM

// fp16 w1, row-major [K_PAD x HID], zero rows 472..479.
__device__ __half g_w1_f16[K_PAD * HID];

// Accurate cos for |x| up to ~1e4: Cody-Waite 2-step reduction + MUFU cos.
__device__ __forceinline__ float fast_cos(float x) {
    float k = rintf(x * 0.15915494309189535f);
    float y = fmaf(-k, 6.28125f, x);
    y = fmaf(-k, 1.9353072e-3f, y);
    return __cosf(y);
}

// ============================ prologue: w1 -> fp16 ============================
__global__ void prep_w1_kernel(const float* __restrict__ w1) {
    int idx = blockIdx.x * blockDim.x + threadIdx.x;   // 0 .. 480*128-1
    int k = idx / HID;
    float v = (k < IN_D) ? w1[idx] : 0.0f;
    g_w1_f16[idx] = __float2half(v);
}

// ============================ main kernel ============================
__global__ void __launch_bounds__(NTHREADS, 2)
tgn_growth_kernel(const int* __restrict__ src, const int* __restrict__ dst,
                  const float* __restrict__ t, const float* __restrict__ edge_attr,
                  const float* __restrict__ memory, const float* __restrict__ last_update,
                  const float* __restrict__ time_w, const float* __restrict__ time_b,
                  const float* __restrict__ b1, const float* __restrict__ w2,
                  const float* __restrict__ b2, float* __restrict__ out) {
    extern __shared__ __align__(16) char smem[];
    const int tid = threadIdx.x;
    const int wid = tid >> 5;
    const int lid = tid & 31;
    const int wm  = wid >> 1;     // 0..3: rows [32wm, 32wm+32)
    const int wn  = wid & 1;      // 0..1: cols [64wn, 64wn+64)

    int*   sSrc = (int*)(smem + SO_SRC);
    int*   sDst = (int*)(smem + SO_DST);
    float* sDt  = (float*)(smem + SO_DT);
    int*   sEof = (int*)(smem + SO_EOF);
    float* sMsk = (float*)(smem + SO_MSK);
    float* sB1  = (float*)(smem + SO_B1);
    float* sW2  = (float*)(smem + SO_W2);
    float* sPart= (float*)(smem + SO_PART);
    __half* sA[2] = { (__half*)(smem + SO_A0), (__half*)(smem + SO_A1) };
    __half* sB[2] = { (__half*)(smem + SO_B0), (__half*)(smem + SO_B1b) };

    // ---- per-tile scalar staging ----
    const int tile0 = blockIdx.x * TILE_M;
    if (tid < TILE_M) {
        int e = tile0 + tid;
        bool v = (e < E_TOTAL);
        int ec = v ? e : 0;
        int s = src[ec];
        sSrc[tid] = s * MEM_D;
        sDst[tid] = dst[ec] * MEM_D;
        sDt[tid]  = t[ec] - last_update[s];
        sEof[tid] = ec * EDGE_D;
        sMsk[tid] = v ? 1.0f : 0.0f;
        sB1[tid]  = b1[tid];
        sW2[tid]  = w2[tid];
    }
    __syncthreads();

    // ---- accumulators: warp covers 32 rows x 64 cols = 2m x 4n tiles ----
    wmma::fragment<wmma::accumulator, 16, 16, 16, float> acc[2][4];
    #pragma unroll
    for (int mt = 0; mt < 2; ++mt)
        #pragma unroll
        for (int nt = 0; nt < 4; ++nt) wmma::fill_fragment(acc[mt][nt], 0.0f);

    // ---- prefetch registers ----
    float2 preA[8];   // 128 rows x 16 pairs / 256 threads
    uint4  preB[2];   // 32 rows x 16 uint4 / 256 threads

    // Load pair source for (r, k0); time region returns time_w pair (cos applied at store).
    auto load_chunk = [&](int kb) {
        #pragma unroll
        for (int j = 0; j < 8; ++j) {
            const int i = tid + j * NTHREADS;
            const int r = i >> 4, jp = i & 15;
            const int k0 = kb + (jp << 1);
            const float* p;
            if (k0 < MEM_D)            p = memory + sSrc[r] + k0;
            else if (k0 < 2 * MEM_D)   p = memory + sDst[r] + (k0 - MEM_D);
            else if (k0 < 300)         p = time_w + (k0 - 200);
            else if (k0 < IN_D)        p = edge_attr + sEof[r] + (k0 - 300);
            else                       p = nullptr;
            preA[j] = p ? *reinterpret_cast<const float2*>(p) : make_float2(0.f, 0.f);
        }
        #pragma unroll
        for (int j = 0; j < 2; ++j) {
            const int i = tid + j * NTHREADS;
            const int row = i >> 4, q = i & 15;
            preB[j] = *reinterpret_cast<const uint4*>(g_w1_f16 + (kb + row) * HID + q * 8);
        }
    };

    auto store_chunk = [&](int kb, __half* bufA, __half* bufB) {
        #pragma unroll
        for (int j = 0; j < 8; ++j) {
            const int i = tid + j * NTHREADS;
            const int r = i >> 4, jp = i & 15;
            const int k0 = kb + (jp << 1);
            float2 v = preA[j];
            float x0, x1;
            if (k0 >= 200 && k0 < 300) {
                float2 tb2 = *reinterpret_cast<const float2*>(time_b + (k0 - 200));
                const float dtv = sDt[r];
                x0 = fast_cos(fmaf(dtv, v.x, tb2.x));
                x1 = fast_cos(fmaf(dtv, v.y, tb2.y));
            } else { x0 = v.x; x1 = v.y; }
            const float m = sMsk[r];
            *reinterpret_cast<__half2*>(bufA + r * A_LD + (jp << 1)) =
                __floats2half2_rn(x0 * m, x1 * m);
        }
        #pragma unroll
        for (int j = 0; j < 2; ++j) {
            const int i = tid + j * NTHREADS;
            const int row = i >> 4, q = i & 15;
            *reinterpret_cast<uint4*>(bufB + row * B_LD + q * 8) = preB[j];
        }
    };

    // ---- pipelined K-chunk loop: one barrier per chunk ----
    load_chunk(0);
    store_chunk(0, sA[0], sB[0]);
    __syncthreads();

    for (int c = 0; c < NCHUNK; ++c) {
        const int cur = c & 1;
        if (c + 1 < NCHUNK) load_chunk((c + 1) * KCHUNK);   // loads fly under WMMA

        const __half* aBase = sA[cur] + (wm * 32) * A_LD;
        const __half* bBase = sB[cur] + wn * 64;
        #pragma unroll
        for (int ks = 0; ks < KCHUNK / 16; ++ks) {
            wmma::fragment<wmma::matrix_a, 16, 16, 16, __half, wmma::row_major> af0, af1;
            wmma::load_matrix_sync(af0, aBase + ks * 16, A_LD);
            wmma::load_matrix_sync(af1, aBase + 16 * A_LD + ks * 16, A_LD);
            #pragma unroll
            for (int nt = 0; nt < 4; ++nt) {
                wmma::fragment<wmma::matrix_b, 16, 16, 16, __half, wmma::row_major> bf;
                wmma::load_matrix_sync(bf, bBase + (ks * 16) * B_LD + nt * 16, B_LD);
                wmma::mma_sync(acc[0][nt], af0, bf, acc[0][nt]);
                wmma::mma_sync(acc[1][nt], af1, bf, acc[1][nt]);
            }
        }

        if (c + 1 < NCHUNK) store_chunk((c + 1) * KCHUNK, sA[cur ^ 1], sB[cur ^ 1]);
        __syncthreads();
    }

    // ---- epilogue: bias + ReLU + dot(w2), per-warp partials over 64-col halves ----
    float* scr = (float*)(smem + SO_A0) + wid * 256;   // warp-private 16x16 scratch
    const int rrow = lid >> 1;
    const int cb   = (lid & 1) * 8;
    float part[2] = {0.0f, 0.0f};
    #pragma unroll
    for (int mt = 0; mt < 2; ++mt) {
        #pragma unroll
        for (int nt = 0; nt < 4; ++nt) {
            __syncwarp();
            wmma::store_matrix_sync(scr, acc[mt][nt], 16, wmma::mem_row_major);
            __syncwarp();
            #pragma unroll
            for (int j = 0; j < 8; ++j) {
                const int h = wn * 64 + nt * 16 + cb + j;
                float v = scr[rrow * 16 + cb + j] + sB1[h];
                v = fmaxf(v, 0.0f);
                part[mt] = fmaf(v, sW2[h], part[mt]);
            }
        }
    }
    #pragma unroll
    for (int mt = 0; mt < 2; ++mt) {
        part[mt] += __shfl_xor_sync(0xFFFFFFFFu, part[mt], 1);
        if ((lid & 1) == 0)
            sPart[wn * 128 + wm * 32 + mt * 16 + rrow] = part[mt];
    }
    __syncthreads();

    if (tid < TILE_M) {
        const int e = tile0 + tid;
        if (e < E_TOTAL) out[e] = sPart[tid] + sPart[128 + tid] + b2[0];
    }
}

// ============================ launch ============================
extern "C" void kernel_launch(void* const* d_in, const int* in_sizes, int n_in,
                              void* d_out, int out_size) {
    (void)in_sizes; (void)n_in; (void)out_size;
    const int*   src         = (const int*)d_in[0];
    const int*   dst         = (const int*)d_in[1];
    const float* t           = (const float*)d_in[2];
    const float* edge_attr   = (const float*)d_in[3];
    const float* memory      = (const float*)d_in[4];
    const float* last_update = (const float*)d_in[5];
    const float* time_w      = (const float*)d_in[6];
    const float* time_b      = (const float*)d_in[7];
    const float* w1          = (const float*)d_in[8];
    const float* b1          = (const float*)d_in[9];
    const float* w2          = (const float*)d_in[10];
    const float* b2          = (const float*)d_in[11];
    float* out = (float*)d_out;

    prep_w1_kernel<<<(K_PAD * HID + 255) / 256, 256>>>(w1);

    cudaFuncSetAttribute(tgn_growth_kernel,
                         cudaFuncAttributeMaxDynamicSharedMemorySize, SMEM_DYN);
    tgn_growth_kernel<<<NUM_TILES, NTHREADS, SMEM_DYN>>>(
        src, dst, t, edge_attr, memory, last_update, time_w, time_b, b1, w2, b2, out);
}

// round 10
// speedup vs baseline: 2.6621x; 1.6565x over previous
#include <cuda_runtime.h>
#include <cuda_fp16.h>
#include <cstdint>

// ============================ problem constants ============================
static constexpr int E_TOTAL = 500000;
static constexpr int MEM_D   = 100;
static constexpr int EDGE_D  = 172;
static constexpr int HID     = 128;
static constexpr int IN_D    = 472;   // 100 + 100 + 100 + 172
static constexpr int K_PAD   = 480;
static constexpr int KCHUNK  = 16;
static constexpr int NCHUNK  = K_PAD / KCHUNK;    // 30
static constexpr int TILE_M  = 128;
static constexpr int NTHREADS = 256;              // 8 warps: 4 wm x 2 wn
static constexpr int NUM_TILES = (E_TOTAL + TILE_M - 1) / TILE_M;  // 3907

static constexpr int B_LD = 136;                  // halves; 272B row stride (16B-mult)
static constexpr int NBUF = 3;                    // cp.async ring depth

// fp16 w1, row-major [K_PAD x HID], zero rows 472..479.
__device__ __align__(16) __half g_w1_f16[K_PAD * HID];

__device__ __forceinline__ uint32_t smem_u32(const void* p) {
    uint32_t a;
    asm("{ .reg .u64 t; cvta.to.shared.u64 t, %1; cvt.u32.u64 %0, t; }" : "=r"(a) : "l"(p));
    return a;
}

// Accurate cos for |x| up to ~1e4: Cody-Waite 2-step reduction + MUFU cos.
__device__ __forceinline__ float fast_cos(float x) {
    float k = rintf(x * 0.15915494309189535f);
    float y = fmaf(-k, 6.28125f, x);
    y = fmaf(-k, 1.9353072e-3f, y);
    return __cosf(y);
}

__device__ __forceinline__ void mma16816(float d[4], const uint32_t a[4],
                                         uint32_t b0, uint32_t b1) {
    asm volatile(
        "mma.sync.aligned.m16n8k16.row.col.f32.f16.f16.f32 "
        "{%0,%1,%2,%3}, {%4,%5,%6,%7}, {%8,%9}, {%0,%1,%2,%3};"
        : "+f"(d[0]), "+f"(d[1]), "+f"(d[2]), "+f"(d[3])
        : "r"(a[0]), "r"(a[1]), "r"(a[2]), "r"(a[3]), "r"(b0), "r"(b1));
}

// ============================ prologue: w1 -> fp16 ============================
__global__ void prep_w1_kernel(const float* __restrict__ w1) {
    int idx = blockIdx.x * blockDim.x + threadIdx.x;   // 0 .. 480*128-1
    int k = idx / HID;
    float v = (k < IN_D) ? w1[idx] : 0.0f;
    g_w1_f16[idx] = __float2half(v);
}

// ============================ main kernel ============================
__global__ void __launch_bounds__(NTHREADS, 2)
tgn_growth_kernel(const int* __restrict__ src, const int* __restrict__ dst,
                  const float* __restrict__ t, const float* __restrict__ edge_attr,
                  const float* __restrict__ memory, const float* __restrict__ last_update,
                  const float* __restrict__ time_w, const float* __restrict__ time_b,
                  const float* __restrict__ b1, const float* __restrict__ w2,
                  const float* __restrict__ b2, float* __restrict__ out) {
    __shared__ int   sSrc[TILE_M], sDst[TILE_M], sEof[TILE_M];
    __shared__ float sDt[TILE_M], sB1f[HID], sW2f[HID], sPart[2 * TILE_M];
    __shared__ __align__(16) __half sB[NBUF][KCHUNK * B_LD];

    const int tid = threadIdx.x;
    const int wid = tid >> 5;
    const int lid = tid & 31;
    const int wm  = wid >> 1;          // rows [32wm, 32wm+32)
    const int wn  = wid & 1;           // cols [64wn, 64wn+64)
    const int rl  = lid >> 2;          // 0..7
    const int c0  = (lid & 3) * 2;     // 0,2,4,6
    const int tile0 = blockIdx.x * TILE_M;

    // B ring addresses + cp.async issue helper state
    uint32_t bAddr[NBUF];
    #pragma unroll
    for (int b = 0; b < NBUF; ++b) bAddr[b] = smem_u32(&sB[b][0]);
    const int brow = tid >> 4;          // 0..15
    const int bseg = tid & 15;          // 0..15
    const uint32_t bDstOff = (uint32_t)(brow * B_LD + bseg * 8) * 2;

    auto issueB = [&](int c, int buf) {
        const __half* gsrc = g_w1_f16 + (c * KCHUNK + brow) * HID + bseg * 8;
        asm volatile("cp.async.cg.shared.global [%0], [%1], 16;"
                     :: "r"(bAddr[buf] + bDstOff), "l"(gsrc) : "memory");
        asm volatile("cp.async.commit_group;" ::: "memory");
    };

    // B chunks 0 and 1 in flight before anything else.
    issueB(0, 0);
    issueB(1, 1);

    // ---- per-tile scalar staging (clamped index; store-guard handles tail) ----
    if (tid < TILE_M) {
        int e  = tile0 + tid;
        int ec = (e < E_TOTAL) ? e : (E_TOTAL - 1);
        int s  = src[ec];
        sSrc[tid] = s * MEM_D;
        sDst[tid] = dst[ec] * MEM_D;
        sDt[tid]  = t[ec] - last_update[s];
        sEof[tid] = ec * EDGE_D;
        sB1f[tid] = b1[tid];
        sW2f[tid] = w2[tid];
    }
    __syncthreads();

    // ---- per-thread row offsets (rows: wm*32 + i*8 + rl, i = 0..3) ----
    int srcO[4], dstO[4], eofO[4];
    float dtv[4];
    #pragma unroll
    for (int i = 0; i < 4; ++i) {
        const int r = wm * 32 + i * 8 + rl;
        srcO[i] = sSrc[r]; dstO[i] = sDst[r]; eofO[i] = sEof[r]; dtv[i] = sDt[r];
    }

    // ---- gather chunk c into fp32 prefetch regs (fragment layout) ----
    float2 pre[8];   // [i=row 0..3][g=kgroup 0..1]
    auto gatherChunk = [&](int c) {
        const int kb = c * KCHUNK;
        #pragma unroll
        for (int i = 0; i < 4; ++i) {
            #pragma unroll
            for (int g = 0; g < 2; ++g) {
                const int k = kb + c0 + g * 8;   // even; pairs never straddle regions
                float2 v;
                if (k < MEM_D) {
                    v = *reinterpret_cast<const float2*>(memory + srcO[i] + k);
                } else if (k < 2 * MEM_D) {
                    v = *reinterpret_cast<const float2*>(memory + dstO[i] + (k - MEM_D));
                } else if (k < 300) {
                    float2 tw2 = *reinterpret_cast<const float2*>(time_w + (k - 200));
                    float2 tb2 = *reinterpret_cast<const float2*>(time_b + (k - 200));
                    v.x = fast_cos(fmaf(dtv[i], tw2.x, tb2.x));
                    v.y = fast_cos(fmaf(dtv[i], tw2.y, tb2.y));
                } else if (k < IN_D) {
                    v = *reinterpret_cast<const float2*>(edge_attr + eofO[i] + (k - 300));
                } else {
                    v = make_float2(0.0f, 0.0f);
                }
                pre[i * 2 + g] = v;
            }
        }
    };

    // ---- accumulators: [mt 0..1][nt 0..7][4] ----
    float acc[2][8][4];
    #pragma unroll
    for (int mt = 0; mt < 2; ++mt)
        #pragma unroll
        for (int nt = 0; nt < 8; ++nt)
            #pragma unroll
            for (int q = 0; q < 4; ++q) acc[mt][nt][q] = 0.0f;

    // ldmatrix lane address: lanes 0..15 supply the 16 k-row pointers.
    const uint32_t ldmBase = (uint32_t)(((lid & 15) * B_LD + wn * 64) * 2);

    gatherChunk(0);

    // ---- main loop, fully unrolled: one barrier per chunk ----
    #pragma unroll
    for (int c = 0; c < NCHUNK; ++c) {
        // Convert prefetched fp32 -> A fragment regs.
        // aR[mt]: {a0a1}=row r,k c0..c0+1 ; {a2a3}=row r+8 ; {a4a5}=row r,k+8 ; {a6a7}=row+8,k+8
        uint32_t aR[2][4];
        #pragma unroll
        for (int mt = 0; mt < 2; ++mt)
            #pragma unroll
            for (int h = 0; h < 2; ++h)
                #pragma unroll
                for (int g = 0; g < 2; ++g) {
                    float2 v = pre[(mt * 2 + h) * 2 + g];
                    __half2 h2 = __floats2half2_rn(v.x, v.y);
                    aR[mt][g * 2 + h] = *reinterpret_cast<uint32_t*>(&h2);
                }

        if (c + 1 < NCHUNK) gatherChunk(c + 1);   // LDGs fly under the MMAs

        if (c == NCHUNK - 1) asm volatile("cp.async.wait_group 0;" ::: "memory");
        else                 asm volatile("cp.async.wait_group 1;" ::: "memory");
        __syncthreads();     // B(c) visible to all; all warps done with buf[(c+2)%3]'s old data

        const uint32_t la = bAddr[c % NBUF] + ldmBase;
        #pragma unroll
        for (int nt = 0; nt < 8; ++nt) {
            uint32_t b0, b1r;
            asm volatile("ldmatrix.sync.aligned.m8n8.x2.trans.shared.b16 {%0,%1}, [%2];"
                         : "=r"(b0), "=r"(b1r) : "r"(la + nt * 16));
            mma16816(acc[0][nt], aR[0], b0, b1r);
            mma16816(acc[1][nt], aR[1], b0, b1r);
        }

        if (c + 2 < NCHUNK) issueB(c + 2, (c + 2) % NBUF);
    }

    // ---- epilogue: bias + ReLU + dot(w2), all in registers + shfl reduce ----
    #pragma unroll
    for (int mt = 0; mt < 2; ++mt) {
        float p1 = 0.0f, p2 = 0.0f;   // rows r and r+8 of this m-tile
        #pragma unroll
        for (int nt = 0; nt < 8; ++nt) {
            const int n0 = wn * 64 + nt * 8 + c0;
            float2 bb = *reinterpret_cast<const float2*>(&sB1f[n0]);
            float2 ww = *reinterpret_cast<const float2*>(&sW2f[n0]);
            const float* d = acc[mt][nt];
            p1 = fmaf(fmaxf(d[0] + bb.x, 0.0f), ww.x, p1);
            p1 = fmaf(fmaxf(d[1] + bb.y, 0.0f), ww.y, p1);
            p2 = fmaf(fmaxf(d[2] + bb.x, 0.0f), ww.x, p2);
            p2 = fmaf(fmaxf(d[3] + bb.y, 0.0f), ww.y, p2);
        }
        p1 += __shfl_xor_sync(0xFFFFFFFFu, p1, 1);
        p1 += __shfl_xor_sync(0xFFFFFFFFu, p1, 2);
        p2 += __shfl_xor_sync(0xFFFFFFFFu, p2, 1);
        p2 += __shfl_xor_sync(0xFFFFFFFFu, p2, 2);
        if ((lid & 3) == 0) {
            const int rbase = wm * 32 + mt * 16 + rl;
            sPart[wn * TILE_M + rbase]     = p1;
            sPart[wn * TILE_M + rbase + 8] = p2;
        }
    }
    __syncthreads();

    if (tid < TILE_M) {
        const int e = tile0 + tid;
        if (e < E_TOTAL) out[e] = sPart[tid] + sPart[TILE_M + tid] + b2[0];
    }
}

// ============================ launch ============================
extern "C" void kernel_launch(void* const* d_in, const int* in_sizes, int n_in,
                              void* d_out, int out_size) {
    (void)in_sizes; (void)n_in; (void)out_size;
    const int*   src         = (const int*)d_in[0];
    const int*   dst         = (const int*)d_in[1];
    const float* t           = (const float*)d_in[2];
    const float* edge_attr   = (const float*)d_in[3];
    const float* memory      = (const float*)d_in[4];
    const float* last_update = (const float*)d_in[5];
    const float* time_w      = (const float*)d_in[6];
    const float* time_b      = (const float*)d_in[7];
    const float* w1          = (const float*)d_in[8];
    const float* b1          = (const float*)d_in[9];
    const float* w2          = (const float*)d_in[10];
    const float* b2          = (const float*)d_in[11];
    float* out = (float*)d_out;

    prep_w1_kernel<<<(K_PAD * HID + 255) / 256, 256>>>(w1);
    tgn_growth_kernel<<<NUM_TILES, NTHREADS>>>(
        src, dst, t, edge_attr, memory, last_update, time_w, time_b, b1, w2, b2, out);
}

// round 11
// speedup vs baseline: 2.7151x; 1.0199x over previous
#include <cuda_runtime.h>
#include <cuda_fp16.h>
#include <cstdint>

// ============================ problem constants ============================
static constexpr int E_TOTAL = 500000;
static constexpr int MEM_D   = 100;
static constexpr int EDGE_D  = 172;
static constexpr int HID     = 128;
static constexpr int IN_D    = 472;   // 100 + 100 + 100 + 172
static constexpr int K_PAD   = 480;
static constexpr int KCHUNK  = 16;
static constexpr int NCHUNK  = K_PAD / KCHUNK;    // 30
static constexpr int TILE_M  = 256;               // edges per tile
static constexpr int NTHREADS = 512;              // 16 warps: 8 wm x 2 wn
static constexpr int NUM_CTAS = 152;              // persistent: one per GB300 SM
static constexpr int NUM_TILES = (E_TOTAL + TILE_M - 1) / TILE_M;  // 1954

static constexpr int B_LD = 136;                  // halves; 272B row stride

// ============================ smem layout (bytes, dynamic) ============================
static constexpr int SO_B    = 0;                             // full W1: 480 x B_LD halves
static constexpr int B_BYTES = K_PAD * B_LD * 2;              // 130560
static constexpr int SO_SRC  = SO_B + B_BYTES;                // int[256]
static constexpr int SO_DST  = SO_SRC + TILE_M * 4;
static constexpr int SO_EOF  = SO_DST + TILE_M * 4;
static constexpr int SO_DT   = SO_EOF + TILE_M * 4;           // float[256]
static constexpr int SO_B1   = SO_DT  + TILE_M * 4;           // float[128]
static constexpr int SO_W2   = SO_B1  + HID * 4;              // float[128]
static constexpr int SO_PART = SO_W2  + HID * 4;              // float[512]
static constexpr int SMEM_DYN = SO_PART + 2 * TILE_M * 4;     // 137728 B

// fp16 w1, row-major [K_PAD x HID], zero rows 472..479.
__device__ __align__(16) __half g_w1_f16[K_PAD * HID];

__device__ __forceinline__ uint32_t smem_u32(const void* p) {
    uint32_t a;
    asm("{ .reg .u64 t; cvta.to.shared.u64 t, %1; cvt.u32.u64 %0, t; }" : "=r"(a) : "l"(p));
    return a;
}

// Accurate cos for |x| up to ~1e4: Cody-Waite 2-step reduction + MUFU cos.
__device__ __forceinline__ float fast_cos(float x) {
    float k = rintf(x * 0.15915494309189535f);
    float y = fmaf(-k, 6.28125f, x);
    y = fmaf(-k, 1.9353072e-3f, y);
    return __cosf(y);
}

__device__ __forceinline__ void mma16816(float d[4], const uint32_t a[4],
                                         uint32_t b0, uint32_t b1) {
    asm volatile(
        "mma.sync.aligned.m16n8k16.row.col.f32.f16.f16.f32 "
        "{%0,%1,%2,%3}, {%4,%5,%6,%7}, {%8,%9}, {%0,%1,%2,%3};"
        : "+f"(d[0]), "+f"(d[1]), "+f"(d[2]), "+f"(d[3])
        : "r"(a[0]), "r"(a[1]), "r"(a[2]), "r"(a[3]), "r"(b0), "r"(b1));
}

// ============================ prologue: w1 -> fp16 ============================
__global__ void prep_w1_kernel(const float* __restrict__ w1) {
    int idx = blockIdx.x * blockDim.x + threadIdx.x;   // 0 .. 480*128-1
    int k = idx / HID;
    float v = (k < IN_D) ? w1[idx] : 0.0f;
    g_w1_f16[idx] = __float2half(v);
}

// ============================ main kernel ============================
__global__ void __launch_bounds__(NTHREADS, 1)
tgn_growth_kernel(const int* __restrict__ src, const int* __restrict__ dst,
                  const float* __restrict__ t, const float* __restrict__ edge_attr,
                  const float* __restrict__ memory, const float* __restrict__ last_update,
                  const float* __restrict__ time_w, const float* __restrict__ time_b,
                  const float* __restrict__ b1, const float* __restrict__ w2,
                  const float* __restrict__ b2, float* __restrict__ out) {
    extern __shared__ __align__(16) char smem[];
    int*   sSrc = (int*)(smem + SO_SRC);
    int*   sDst = (int*)(smem + SO_DST);
    int*   sEof = (int*)(smem + SO_EOF);
    float* sDt  = (float*)(smem + SO_DT);
    float* sB1f = (float*)(smem + SO_B1);
    float* sW2f = (float*)(smem + SO_W2);
    float* sPart= (float*)(smem + SO_PART);

    const int tid = threadIdx.x;
    const int wid = tid >> 5;
    const int lid = tid & 31;
    const int wm  = wid >> 1;          // 0..7: rows [32wm, 32wm+32)
    const int wn  = wid & 1;           // 0..1: cols [64wn, 64wn+64)
    const int rl  = lid >> 2;          // 0..7
    const int c0  = (lid & 3) * 2;     // 0,2,4,6

    // ---- load full W1 into smem once (cp.async, one wait) ----
    const uint32_t bBase = smem_u32(smem + SO_B);
    for (int i = tid; i < K_PAD * 16; i += NTHREADS) {    // 16B segs: 480 rows x 16
        const int row = i >> 4, seg = i & 15;
        const __half* gsrc = g_w1_f16 + row * HID + seg * 8;
        asm volatile("cp.async.cg.shared.global [%0], [%1], 16;"
                     :: "r"(bBase + (uint32_t)(row * B_LD + seg * 8) * 2), "l"(gsrc)
                     : "memory");
    }
    asm volatile("cp.async.commit_group;" ::: "memory");
    if (tid < HID) { sB1f[tid] = b1[tid]; sW2f[tid] = w2[tid]; }
    const float bias2 = b2[0];
    asm volatile("cp.async.wait_group 0;" ::: "memory");
    __syncthreads();

    // ldmatrix lane address (col-block base); chunk c adds c*16*B_LD*2.
    const uint32_t ldmBase = bBase + (uint32_t)(((lid & 15) * B_LD + wn * 64) * 2);

    // ---- persistent tile loop ----
    for (int tile = blockIdx.x; tile < NUM_TILES; tile += NUM_CTAS) {
        const int tile0 = tile * TILE_M;

        __syncthreads();   // protect sSrc/sPart from previous tile's readers
        if (tid < TILE_M) {
            int e  = tile0 + tid;
            int ec = (e < E_TOTAL) ? e : (E_TOTAL - 1);
            int s  = src[ec];
            sSrc[tid] = s * MEM_D;
            sDst[tid] = dst[ec] * MEM_D;
            sDt[tid]  = t[ec] - last_update[s];
            sEof[tid] = ec * EDGE_D;
        }
        __syncthreads();

        // per-thread row offsets: rows wm*32 + i*8 + rl, i = 0..3
        int srcO[4], dstO[4], eofO[4];
        float dtv[4];
        #pragma unroll
        for (int i = 0; i < 4; ++i) {
            const int r = wm * 32 + i * 8 + rl;
            srcO[i] = sSrc[r]; dstO[i] = sDst[r]; eofO[i] = sEof[r]; dtv[i] = sDt[r];
        }

        float2 pre[8];
        auto gatherChunk = [&](int c) {
            const int kb = c * KCHUNK;
            #pragma unroll
            for (int i = 0; i < 4; ++i) {
                #pragma unroll
                for (int g = 0; g < 2; ++g) {
                    const int k = kb + c0 + g * 8;   // even; pairs never straddle regions
                    float2 v;
                    if (k < MEM_D) {
                        v = *reinterpret_cast<const float2*>(memory + srcO[i] + k);
                    } else if (k < 2 * MEM_D) {
                        v = *reinterpret_cast<const float2*>(memory + dstO[i] + (k - MEM_D));
                    } else if (k < 300) {
                        float2 tw2 = *reinterpret_cast<const float2*>(time_w + (k - 200));
                        float2 tb2 = *reinterpret_cast<const float2*>(time_b + (k - 200));
                        v.x = fast_cos(fmaf(dtv[i], tw2.x, tb2.x));
                        v.y = fast_cos(fmaf(dtv[i], tw2.y, tb2.y));
                    } else if (k < IN_D) {
                        v = *reinterpret_cast<const float2*>(edge_attr + eofO[i] + (k - 300));
                    } else {
                        v = make_float2(0.0f, 0.0f);
                    }
                    pre[i * 2 + g] = v;
                }
            }
        };

        float acc[2][8][4];
        #pragma unroll
        for (int mt = 0; mt < 2; ++mt)
            #pragma unroll
            for (int nt = 0; nt < 8; ++nt)
                #pragma unroll
                for (int q = 0; q < 4; ++q) acc[mt][nt][q] = 0.0f;

        gatherChunk(0);

        // ---- barrier-free mainloop: B is resident, warps fully decoupled ----
        #pragma unroll
        for (int c = 0; c < NCHUNK; ++c) {
            uint32_t aR[2][4];
            #pragma unroll
            for (int mt = 0; mt < 2; ++mt)
                #pragma unroll
                for (int h = 0; h < 2; ++h)
                    #pragma unroll
                    for (int g = 0; g < 2; ++g) {
                        float2 v = pre[(mt * 2 + h) * 2 + g];
                        __half2 h2 = __floats2half2_rn(v.x, v.y);
                        aR[mt][g * 2 + h] = *reinterpret_cast<uint32_t*>(&h2);
                    }

            if (c + 1 < NCHUNK) gatherChunk(c + 1);   // LDGs fly under the MMAs

            const uint32_t la = ldmBase + (uint32_t)(c * KCHUNK * B_LD * 2);
            #pragma unroll
            for (int nt = 0; nt < 8; ++nt) {
                uint32_t b0, b1r;
                asm volatile("ldmatrix.sync.aligned.m8n8.x2.trans.shared.b16 {%0,%1}, [%2];"
                             : "=r"(b0), "=r"(b1r) : "r"(la + nt * 16));
                mma16816(acc[0][nt], aR[0], b0, b1r);
                mma16816(acc[1][nt], aR[1], b0, b1r);
            }
        }

        // ---- epilogue: bias + ReLU + dot(w2) in regs, shfl reduce ----
        #pragma unroll
        for (int mt = 0; mt < 2; ++mt) {
            float p1 = 0.0f, p2 = 0.0f;
            #pragma unroll
            for (int nt = 0; nt < 8; ++nt) {
                const int n0 = wn * 64 + nt * 8 + c0;
                float2 bb = *reinterpret_cast<const float2*>(&sB1f[n0]);
                float2 ww = *reinterpret_cast<const float2*>(&sW2f[n0]);
                const float* d = acc[mt][nt];
                p1 = fmaf(fmaxf(d[0] + bb.x, 0.0f), ww.x, p1);
                p1 = fmaf(fmaxf(d[1] + bb.y, 0.0f), ww.y, p1);
                p2 = fmaf(fmaxf(d[2] + bb.x, 0.0f), ww.x, p2);
                p2 = fmaf(fmaxf(d[3] + bb.y, 0.0f), ww.y, p2);
            }
            p1 += __shfl_xor_sync(0xFFFFFFFFu, p1, 1);
            p1 += __shfl_xor_sync(0xFFFFFFFFu, p1, 2);
            p2 += __shfl_xor_sync(0xFFFFFFFFu, p2, 1);
            p2 += __shfl_xor_sync(0xFFFFFFFFu, p2, 2);
            if ((lid & 3) == 0) {
                const int rbase = wm * 32 + mt * 16 + rl;
                sPart[wn * TILE_M + rbase]     = p1;
                sPart[wn * TILE_M + rbase + 8] = p2;
            }
        }
        __syncthreads();

        if (tid < TILE_M) {
            const int e = tile0 + tid;
            if (e < E_TOTAL) out[e] = sPart[tid] + sPart[TILE_M + tid] + bias2;
        }
    }
}

// ============================ launch ============================
extern "C" void kernel_launch(void* const* d_in, const int* in_sizes, int n_in,
                              void* d_out, int out_size) {
    (void)in_sizes; (void)n_in; (void)out_size;
    const int*   src         = (const int*)d_in[0];
    const int*   dst         = (const int*)d_in[1];
    const float* t           = (const float*)d_in[2];
    const float* edge_attr   = (const float*)d_in[3];
    const float* memory      = (const float*)d_in[4];
    const float* last_update = (const float*)d_in[5];
    const float* time_w      = (const float*)d_in[6];
    const float* time_b      = (const float*)d_in[7];
    const float* w1          = (const float*)d_in[8];
    const float* b1          = (const float*)d_in[9];
    const float* w2          = (const float*)d_in[10];
    const float* b2          = (const float*)d_in[11];
    float* out = (float*)d_out;

    prep_w1_kernel<<<(K_PAD * HID + 255) / 256, 256>>>(w1);

    cudaFuncSetAttribute(tgn_growth_kernel,
                         cudaFuncAttributeMaxDynamicSharedMemorySize, SMEM_DYN);
    tgn_growth_kernel<<<NUM_CTAS, NTHREADS, SMEM_DYN>>>(
        src, dst, t, edge_attr, memory, last_update, time_w, time_b, b1, w2, b2, out);
}